// round 1
// baseline (speedup 1.0000x reference)
#include <cuda_runtime.h>
#include <math.h>

#define NG 8192      // graphs
#define L  64        // seq len
#define D  128       // input = hidden dim
#define G4 512       // 4*H gate columns
#define GB 32        // graphs per CTA
#define NT 256       // threads per CTA
#define KC 32        // k-chunk staged per sync
#define AP (D + 4)   // padded A row stride (floats)
#define WP (KC + 1)  // padded W row stride (floats) -- odd => conflict-free

// ---- shared memory layout (floats) ----
#define XS_OFF 0
#define HS_OFF (GB * AP)                    // 4224
#define WB_OFF (2 * GB * AP)                // 8448
#define SC_OFF (WB_OFF + G4 * WP)           // 8448 + 16896 = 25344
#define BI_OFF (SC_OFF + GB * L)            // +2048 = 27392
#define WA_OFF (BI_OFF + G4)                // +512  = 27904
#define SMEM_FLOATS (WA_OFF + D)            // 28032
#define SMEM_BYTES (SMEM_FLOATS * 4)        // 112128 B -> 2 CTAs/SM

// hidden-state scratch for attention pass: 8192*64*128 fp32 = 256 MB
__device__ float hs_buf[(size_t)NG * L * D];

__device__ __forceinline__ float sigf(float v) {
    return 1.0f / (1.0f + expf(-v));
}

extern "C" __global__ void __launch_bounds__(NT)
lstm_att_kernel(const float* __restrict__ x,
                const float* __restrict__ W_ih,
                const float* __restrict__ W_hh,
                const float* __restrict__ b_ih,
                const float* __restrict__ b_hh,
                const float* __restrict__ W_att,
                const float* __restrict__ b_att,
                float* __restrict__ out)
{
    extern __shared__ float sm[];
    float* Xs = sm + XS_OFF;   // [GB][AP]  x_t tile
    float* Hs = sm + HS_OFF;   // [GB][AP]  h tile
    float* Wb = sm + WB_OFF;   // [G4][WP]  W k-chunk
    float* Sc = sm + SC_OFF;   // [GB][L]   attention scores
    float* Bi = sm + BI_OFF;   // [G4]      b_ih + b_hh
    float* Wa = sm + WA_OFF;   // [D]       W_att

    const int tid    = threadIdx.x;
    const int lane   = tid & 31;
    const int warp   = tid >> 5;       // 8 warps: warp w owns graphs 4w..4w+3
    const int g0     = warp << 2;
    const int graph0 = blockIdx.x * GB;

    for (int i = tid; i < G4; i += NT) Bi[i] = b_ih[i] + b_hh[i];
    for (int i = tid; i < D;  i += NT) Wa[i] = W_att[i];
    for (int i = tid; i < GB * AP; i += NT) Hs[i] = 0.0f;

    // cell state lives in registers: [graph r][hidden jj] at j = jj*32 + lane
    float creg[4][4];
    #pragma unroll
    for (int r = 0; r < 4; r++)
        #pragma unroll
        for (int j = 0; j < 4; j++) creg[r][j] = 0.0f;

    const float batt = b_att[0];
    __syncthreads();

    for (int t = 0; t < L; t++) {
        // ---- stage x_t tile: [GB][D], rows 512B each, coalesced float4 ----
        for (int i = tid; i < GB * (D / 4); i += NT) {
            int g = i >> 5, v = i & 31;
            const float4 xv =
                *((const float4*)(x + ((size_t)(graph0 + g) * L + t) * D) + v);
            *(float4*)(Xs + g * AP + v * 4) = xv;
        }

        // ---- accumulators: acc[r][gate*4+jj], init with combined bias ----
        float acc[4][16];
        #pragma unroll
        for (int q = 0; q < 16; q++) {
            int gate = q >> 2, jj = q & 3;
            float b = Bi[gate * 128 + jj * 32 + lane];
            acc[0][q] = b; acc[1][q] = b; acc[2][q] = b; acc[3][q] = b;
        }

        // ---- gates = [x_t ; h] @ [W_ih ; W_hh]^T : two phases x 4 k-chunks ----
        #pragma unroll 1
        for (int p = 0; p < 2; p++) {
            const float* W = p ? W_hh : W_ih;
            const float* A = (p ? Hs : Xs) + g0 * AP;
            #pragma unroll 1
            for (int kc = 0; kc < D / KC; kc++) {
                __syncthreads();   // Wb free of prior readers; staging visible
                // stage W chunk [G4][KC] into smem (stride 33: conflict-free)
                for (int i = tid; i < G4 * (KC / 4); i += NT) {
                    int c = i >> 3, v = i & 7;
                    float4 wv = *(const float4*)(W + c * D + kc * KC + v * 4);
                    float* dst = Wb + c * WP + v * 4;
                    dst[0] = wv.x; dst[1] = wv.y; dst[2] = wv.z; dst[3] = wv.w;
                }
                __syncthreads();

                const float* Ak  = A + kc * KC;
                const float* wbl = Wb + lane * WP;   // lane stride 33 -> bank = lane
                #pragma unroll 4
                for (int kk = 0; kk < KC; kk++) {
                    float a0 = Ak[0 * AP + kk];   // warp-broadcast LDS
                    float a1 = Ak[1 * AP + kk];
                    float a2 = Ak[2 * AP + kk];
                    float a3 = Ak[3 * AP + kk];
                    #pragma unroll
                    for (int q = 0; q < 16; q++) {
                        int gate = q >> 2, jj = q & 3;
                        float b = wbl[(gate * 128 + jj * 32) * WP + kk];
                        acc[0][q] = fmaf(a0, b, acc[0][q]);
                        acc[1][q] = fmaf(a1, b, acc[1][q]);
                        acc[2][q] = fmaf(a2, b, acc[2][q]);
                        acc[3][q] = fmaf(a3, b, acc[3][q]);
                    }
                }
            }
        }
        __syncthreads();   // all Hs reads done before anyone rewrites Hs

        // ---- activations, state update, score, hidden-state spill ----
        #pragma unroll
        for (int r = 0; r < 4; r++) {
            float sc = 0.0f;
            #pragma unroll
            for (int jj = 0; jj < 4; jj++) {
                float ig = sigf(acc[r][0 * 4 + jj]);
                float fg = sigf(acc[r][1 * 4 + jj]);
                float gg = tanhf(acc[r][2 * 4 + jj]);
                float og = sigf(acc[r][3 * 4 + jj]);
                float c  = fg * creg[r][jj] + ig * gg;
                creg[r][jj] = c;
                float h  = og * tanhf(c);
                int j = jj * 32 + lane;
                Hs[(g0 + r) * AP + j] = h;
                hs_buf[((size_t)(graph0 + g0 + r) * L + t) * D + j] = h;
                sc = fmaf(h, Wa[j], sc);
            }
            #pragma unroll
            for (int o = 16; o; o >>= 1)
                sc += __shfl_xor_sync(0xffffffffu, sc, o);
            if (lane == 0) Sc[(g0 + r) * L + t] = sc + batt;
        }
        // safe: next iter's Xs staging only overwrites data whose readers
        // all passed the post-GEMM __syncthreads above.
    }
    __syncthreads();

    // ---- attention pooling: each warp handles its own 4 graphs ----
    #pragma unroll 1
    for (int r = 0; r < 4; r++) {
        int g = g0 + r;
        float s1 = Sc[g * L + lane], s2 = Sc[g * L + 32 + lane];
        float m = fmaxf(s1, s2);
        #pragma unroll
        for (int o = 16; o; o >>= 1)
            m = fmaxf(m, __shfl_xor_sync(0xffffffffu, m, o));
        float e1 = expf(s1 - m), e2 = expf(s2 - m);
        float z = e1 + e2;
        #pragma unroll
        for (int o = 16; o; o >>= 1)
            z += __shfl_xor_sync(0xffffffffu, z, o);
        float inv = 1.0f / z;
        Sc[g * L + lane] = e1 * inv;
        Sc[g * L + 32 + lane] = e2 * inv;
        __syncwarp();

        float a0 = 0.f, a1 = 0.f, a2 = 0.f, a3 = 0.f;
        const float* hp = hs_buf + (size_t)(graph0 + g) * L * D;
        for (int tt = 0; tt < L; tt++) {
            float wt = Sc[g * L + tt];
            a0 = fmaf(wt, hp[tt * D +  0 + lane], a0);
            a1 = fmaf(wt, hp[tt * D + 32 + lane], a1);
            a2 = fmaf(wt, hp[tt * D + 64 + lane], a2);
            a3 = fmaf(wt, hp[tt * D + 96 + lane], a3);
        }
        float* op = out + (size_t)(graph0 + g) * D;
        op[ 0 + lane] = a0;
        op[32 + lane] = a1;
        op[64 + lane] = a2;
        op[96 + lane] = a3;
    }
}

extern "C" void kernel_launch(void* const* d_in, const int* in_sizes, int n_in,
                              void* d_out, int out_size)
{
    const float* x     = (const float*)d_in[0];
    // d_in[1] = batch (int32) -- structurally arange(N)//L, unused
    const float* W_ih  = (const float*)d_in[2];
    const float* W_hh  = (const float*)d_in[3];
    const float* b_ih  = (const float*)d_in[4];
    const float* b_hh  = (const float*)d_in[5];
    const float* W_att = (const float*)d_in[6];
    const float* b_att = (const float*)d_in[7];
    float* out = (float*)d_out;

    cudaFuncSetAttribute(lstm_att_kernel,
                         cudaFuncAttributeMaxDynamicSharedMemorySize, SMEM_BYTES);
    lstm_att_kernel<<<NG / GB, NT, SMEM_BYTES>>>(
        x, W_ih, W_hh, b_ih, b_hh, W_att, b_att, out);
}

// round 3
// speedup vs baseline: 1.1255x; 1.1255x over previous
#include <cuda_runtime.h>
#include <string.h>

#define NG 8192      // graphs
#define L  64        // seq len
#define D  128       // input = hidden dim
#define G4 512       // 4*H gate columns
#define GB 32        // graphs per CTA
#define NT 256       // threads per CTA
#define KC 64        // k-chunk staged per sync
#define AP (D + 4)   // padded A row stride (floats): 132 (16B-aligned rows)
#define WP (KC + 2)  // padded W row stride: 66 -> lane-pair banks 2l,2l+1 conflict-free

// ---- shared memory layout (floats) ----
#define XS_OFF 0
#define HS_OFF (GB * AP)                    // 4224
#define WB_OFF (2 * GB * AP)                // 8448
#define SC_OFF (WB_OFF + G4 * WP)           // 8448 + 33792 = 42240
#define BI_OFF (SC_OFF + GB * L)            // +2048 = 44288
#define WA_OFF (BI_OFF + G4)                // +512  = 44800
#define SMEM_FLOATS (WA_OFF + D)            // 44928
#define SMEM_BYTES (SMEM_FLOATS * 4)        // 179712 B -> 1 CTA/SM

typedef unsigned long long ull;

// hidden-state scratch for attention pass: 8192*64*128 fp32 = 256 MB
__device__ float hs_buf[(size_t)NG * L * D];

// ---- packed fp32x2 helpers ----
__device__ __forceinline__ ull pk2(float lo, float hi) {
    float2 f = make_float2(lo, hi);
    ull u; memcpy(&u, &f, 8); return u;
}
__device__ __forceinline__ float upk_sum(ull u) {
    float2 f; memcpy(&f, &u, 8); return f.x + f.y;
}
__device__ __forceinline__ void fma2(ull& d, ull a, ull b) {
    asm("fma.rn.f32x2 %0, %1, %2, %0;" : "+l"(d) : "l"(a), "l"(b));
}

// ---- fast transcendentals (MUFU, rel err ~1e-7: safe vs 1e-3 budget) ----
__device__ __forceinline__ float ex2a(float x) {
    float y; asm("ex2.approx.f32 %0, %1;" : "=f"(y) : "f"(x)); return y;
}
__device__ __forceinline__ float rcpa(float x) {
    float y; asm("rcp.approx.f32 %0, %1;" : "=f"(y) : "f"(x)); return y;
}
__device__ __forceinline__ float sigf(float x) {
    return rcpa(1.0f + ex2a(-1.4426950408889634f * x));
}
__device__ __forceinline__ float tanhf_(float x) {
    return fmaf(2.0f, rcpa(1.0f + ex2a(-2.8853900817779268f * x)), -1.0f);
}

extern "C" __global__ void __launch_bounds__(NT, 1)
lstm_att_kernel(const float* __restrict__ x,
                const float* __restrict__ W_ih,
                const float* __restrict__ W_hh,
                const float* __restrict__ b_ih,
                const float* __restrict__ b_hh,
                const float* __restrict__ W_att,
                const float* __restrict__ b_att,
                float* __restrict__ out)
{
    extern __shared__ float sm[];
    float* Xs = sm + XS_OFF;   // [GB][AP]  x_t tile
    float* Hs = sm + HS_OFF;   // [GB][AP]  h tile
    float* Wb = sm + WB_OFF;   // [G4][WP]  W k-chunk (row stride 66)
    float* Sc = sm + SC_OFF;   // [GB][L]   attention scores
    float* Bi = sm + BI_OFF;   // [G4]      b_ih + b_hh
    float* Wa = sm + WA_OFF;   // [D]       W_att

    const int tid    = threadIdx.x;
    const int lane   = tid & 31;
    const int warp   = tid >> 5;       // 8 warps: warp w owns graphs 4w..4w+3
    const int g0     = warp << 2;
    const int graph0 = blockIdx.x * GB;

    for (int i = tid; i < G4; i += NT) Bi[i] = b_ih[i] + b_hh[i];
    for (int i = tid; i < D;  i += NT) Wa[i] = W_att[i];
    for (int i = tid; i < GB * AP; i += NT) Hs[i] = 0.0f;

    // cell state in registers: [graph r][hidden jj], j = jj*32 + lane
    float creg[4][4];
    #pragma unroll
    for (int r = 0; r < 4; r++)
        #pragma unroll
        for (int j = 0; j < 4; j++) creg[r][j] = 0.0f;

    const float batt = b_att[0];
    __syncthreads();

    for (int t = 0; t < L; t++) {
        // ---- stage x_t tile: [GB][D], coalesced float4 (Xs rows 16B-aligned) ----
        for (int i = tid; i < GB * (D / 4); i += NT) {
            int g = i >> 5, v = i & 31;
            const float4 xv =
                *((const float4*)(x + ((size_t)(graph0 + g) * L + t) * D) + v);
            *(float4*)(Xs + g * AP + v * 4) = xv;
        }

        // ---- packed accumulators: acc[r][q] = (even-k sum + bias, odd-k sum) ----
        ull acc[4][16];
        #pragma unroll
        for (int q = 0; q < 16; q++) {
            float b = Bi[(q >> 2) * 128 + (q & 3) * 32 + lane];
            ull v = pk2(b, 0.0f);
            acc[0][q] = v; acc[1][q] = v; acc[2][q] = v; acc[3][q] = v;
        }

        // ---- gates = [x_t ; h] @ [W_ih ; W_hh]^T ----
        #pragma unroll 1
        for (int p = 0; p < 2; p++) {
            const float* W = p ? W_hh : W_ih;
            const float* A = (p ? Hs : Xs) + g0 * AP;
            #pragma unroll 1
            for (int kc = 0; kc < D / KC; kc++) {
                __syncthreads();   // prior Wb readers done
                // stage W chunk [G4][KC]: LDG.128 + 2x STS.64
                // (Wb rows only 8B-aligned: stride 66 floats => NO float4 stores)
                for (int i = tid; i < G4 * (KC / 4); i += NT) {
                    int c = i >> 4, v = i & 15;
                    float4 wv = *(const float4*)(W + c * D + kc * KC + v * 4);
                    ull* dst = (ull*)(Wb + c * WP + v * 4);   // 8B aligned
                    dst[0] = pk2(wv.x, wv.y);
                    dst[1] = pk2(wv.z, wv.w);
                }
                __syncthreads();

                const float* Ak = A + kc * KC;
                const float* wl = Wb + lane * WP;   // lane's column base
                #pragma unroll 2
                for (int kp = 0; kp < KC / 2; kp++) {
                    // a pairs: broadcast LDS.64 per graph row
                    ull a0 = *(const ull*)(Ak + 0 * AP + 2 * kp);
                    ull a1 = *(const ull*)(Ak + 1 * AP + 2 * kp);
                    ull a2 = *(const ull*)(Ak + 2 * AP + 2 * kp);
                    ull a3 = *(const ull*)(Ak + 3 * AP + 2 * kp);
                    const float* wk = wl + 2 * kp;
                    #pragma unroll
                    for (int q = 0; q < 16; q++) {
                        const int off = ((q >> 2) * 128 + (q & 3) * 32) * WP;
                        ull b2 = *(const ull*)(wk + off);   // LDS.64, banks 2l,2l+1
                        fma2(acc[0][q], a0, b2);
                        fma2(acc[1][q], a1, b2);
                        fma2(acc[2][q], a2, b2);
                        fma2(acc[3][q], a3, b2);
                    }
                }
            }
        }
        __syncthreads();   // all Hs reads done before rewriting Hs

        // ---- activations, state update, score, hidden-state spill ----
        #pragma unroll
        for (int r = 0; r < 4; r++) {
            float sc = 0.0f;
            #pragma unroll
            for (int jj = 0; jj < 4; jj++) {
                float iv = sigf(upk_sum(acc[r][0 * 4 + jj]));
                float fv = sigf(upk_sum(acc[r][1 * 4 + jj]));
                float gv = tanhf_(upk_sum(acc[r][2 * 4 + jj]));
                float ov = sigf(upk_sum(acc[r][3 * 4 + jj]));
                float c  = fv * creg[r][jj] + iv * gv;
                creg[r][jj] = c;
                float h  = ov * tanhf_(c);
                int j = jj * 32 + lane;
                Hs[(g0 + r) * AP + j] = h;
                hs_buf[((size_t)(graph0 + g0 + r) * L + t) * D + j] = h;
                sc = fmaf(h, Wa[j], sc);
            }
            #pragma unroll
            for (int o = 16; o; o >>= 1)
                sc += __shfl_xor_sync(0xffffffffu, sc, o);
            if (lane == 0) Sc[(g0 + r) * L + t] = sc + batt;
        }
    }
    __syncthreads();

    // ---- attention pooling: each warp handles its own 4 graphs ----
    #pragma unroll 1
    for (int r = 0; r < 4; r++) {
        int g = g0 + r;
        float s1 = Sc[g * L + lane], s2 = Sc[g * L + 32 + lane];
        float m = fmaxf(s1, s2);
        #pragma unroll
        for (int o = 16; o; o >>= 1)
            m = fmaxf(m, __shfl_xor_sync(0xffffffffu, m, o));
        float e1 = ex2a(1.4426950408889634f * (s1 - m));
        float e2 = ex2a(1.4426950408889634f * (s2 - m));
        float z = e1 + e2;
        #pragma unroll
        for (int o = 16; o; o >>= 1)
            z += __shfl_xor_sync(0xffffffffu, z, o);
        float inv = rcpa(z);
        Sc[g * L + lane] = e1 * inv;
        Sc[g * L + 32 + lane] = e2 * inv;
        __syncwarp();

        float a0 = 0.f, a1 = 0.f, a2 = 0.f, a3 = 0.f;
        const float* hp = hs_buf + (size_t)(graph0 + g) * L * D;
        for (int tt = 0; tt < L; tt++) {
            float wt = Sc[g * L + tt];
            a0 = fmaf(wt, hp[tt * D +  0 + lane], a0);
            a1 = fmaf(wt, hp[tt * D + 32 + lane], a1);
            a2 = fmaf(wt, hp[tt * D + 64 + lane], a2);
            a3 = fmaf(wt, hp[tt * D + 96 + lane], a3);
        }
        float* op = out + (size_t)(graph0 + g) * D;
        op[ 0 + lane] = a0;
        op[32 + lane] = a1;
        op[64 + lane] = a2;
        op[96 + lane] = a3;
    }
}

extern "C" void kernel_launch(void* const* d_in, const int* in_sizes, int n_in,
                              void* d_out, int out_size)
{
    const float* x     = (const float*)d_in[0];
    // d_in[1] = batch (int32) -- structurally arange(N)//L, unused
    const float* W_ih  = (const float*)d_in[2];
    const float* W_hh  = (const float*)d_in[3];
    const float* b_ih  = (const float*)d_in[4];
    const float* b_hh  = (const float*)d_in[5];
    const float* W_att = (const float*)d_in[6];
    const float* b_att = (const float*)d_in[7];
    float* out = (float*)d_out;

    cudaFuncSetAttribute(lstm_att_kernel,
                         cudaFuncAttributeMaxDynamicSharedMemorySize, SMEM_BYTES);
    lstm_att_kernel<<<NG / GB, NT, SMEM_BYTES>>>(
        x, W_ih, W_hh, b_ih, b_hh, W_att, b_att, out);
}

// round 4
// speedup vs baseline: 1.1261x; 1.0005x over previous
#include <cuda_runtime.h>
#include <string.h>

#define NG 8192      // graphs
#define L  64        // seq len
#define D  128       // input = hidden dim
#define G4 512       // 4*H gate columns
#define GB 32        // graphs per CTA
#define NT 256       // threads per CTA
#define KC 64        // k-chunk staged per sync
#define AP (D + 4)   // padded A row stride (floats): 132 (16B-aligned rows)
#define WP (KC + 2)  // padded W row stride: 66 -> lane-pair banks 2l,2l+1 conflict-free

// ---- shared memory layout (floats) ----
#define XS_OFF 0
#define HS_OFF (GB * AP)                    // 4224
#define WB_OFF (2 * GB * AP)                // 8448
#define SC_OFF (WB_OFF + G4 * WP)           // 8448 + 33792 = 42240
#define BI_OFF (SC_OFF + GB * L)            // +2048 = 44288
#define WA_OFF (BI_OFF + G4)                // +512  = 44800
#define SMEM_FLOATS (WA_OFF + D)            // 44928
#define SMEM_BYTES (SMEM_FLOATS * 4)        // 179712 B -> 1 CTA/SM

typedef unsigned long long ull;

// hidden-state scratch for attention pass: 8192*64*128 fp32 = 256 MB
__device__ float hs_buf[(size_t)NG * L * D];

// ---- packed fp32x2 helpers ----
__device__ __forceinline__ ull pk2(float lo, float hi) {
    float2 f = make_float2(lo, hi);
    ull u; memcpy(&u, &f, 8); return u;
}
__device__ __forceinline__ float upk_sum(ull u) {
    float2 f; memcpy(&f, &u, 8); return f.x + f.y;
}
__device__ __forceinline__ void fma2(ull& d, ull a, ull b) {
    asm("fma.rn.f32x2 %0, %1, %2, %0;" : "+l"(d) : "l"(a), "l"(b));
}

// ---- fast transcendentals (MUFU, rel err ~1e-7: safe vs 1e-3 budget) ----
__device__ __forceinline__ float ex2a(float x) {
    float y; asm("ex2.approx.f32 %0, %1;" : "=f"(y) : "f"(x)); return y;
}
__device__ __forceinline__ float rcpa(float x) {
    float y; asm("rcp.approx.f32 %0, %1;" : "=f"(y) : "f"(x)); return y;
}
__device__ __forceinline__ float sigf(float x) {
    return rcpa(1.0f + ex2a(-1.4426950408889634f * x));
}
__device__ __forceinline__ float tanhf_(float x) {
    return fmaf(2.0f, rcpa(1.0f + ex2a(-2.8853900817779268f * x)), -1.0f);
}

extern "C" __global__ void __launch_bounds__(NT, 1)
lstm_att_kernel(const float* __restrict__ x,
                const float* __restrict__ W_ih,
                const float* __restrict__ W_hh,
                const float* __restrict__ b_ih,
                const float* __restrict__ b_hh,
                const float* __restrict__ W_att,
                const float* __restrict__ b_att,
                float* __restrict__ out)
{
    extern __shared__ float sm[];
    float* Xs = sm + XS_OFF;   // [GB][AP]  x_t tile
    float* Hs = sm + HS_OFF;   // [GB][AP]  h tile
    float* Wb = sm + WB_OFF;   // [G4][WP]  W k-chunk (row stride 66)
    float* Sc = sm + SC_OFF;   // [GB][L]   attention scores
    float* Bi = sm + BI_OFF;   // [G4]      b_ih + b_hh
    float* Wa = sm + WA_OFF;   // [D]       W_att

    const int tid    = threadIdx.x;
    const int lane   = tid & 31;
    const int warp   = tid >> 5;       // 8 warps: warp w owns graphs 4w..4w+3
    const int g0     = warp << 2;
    const int graph0 = blockIdx.x * GB;

    for (int i = tid; i < G4; i += NT) Bi[i] = b_ih[i] + b_hh[i];
    for (int i = tid; i < D;  i += NT) Wa[i] = W_att[i];
    for (int i = tid; i < GB * AP; i += NT) Hs[i] = 0.0f;

    // cell state in registers: [graph r][hidden jj], j = jj*32 + lane
    float creg[4][4];
    #pragma unroll
    for (int r = 0; r < 4; r++)
        #pragma unroll
        for (int j = 0; j < 4; j++) creg[r][j] = 0.0f;

    const float batt = b_att[0];
    __syncthreads();

    for (int t = 0; t < L; t++) {
        // ---- stage x_t tile: [GB][D], coalesced float4 (Xs rows 16B-aligned) ----
        for (int i = tid; i < GB * (D / 4); i += NT) {
            int g = i >> 5, v = i & 31;
            const float4 xv =
                *((const float4*)(x + ((size_t)(graph0 + g) * L + t) * D) + v);
            *(float4*)(Xs + g * AP + v * 4) = xv;
        }

        // ---- packed accumulators: acc[r][q] = (even-k sum + bias, odd-k sum) ----
        ull acc[4][16];
        #pragma unroll
        for (int q = 0; q < 16; q++) {
            float b = Bi[(q >> 2) * 128 + (q & 3) * 32 + lane];
            ull v = pk2(b, 0.0f);
            acc[0][q] = v; acc[1][q] = v; acc[2][q] = v; acc[3][q] = v;
        }

        // ---- gates = [x_t ; h] @ [W_ih ; W_hh]^T ----
        #pragma unroll 1
        for (int p = 0; p < 2; p++) {
            const float* W = p ? W_hh : W_ih;
            const float* A = (p ? Hs : Xs) + g0 * AP;
            #pragma unroll 1
            for (int kc = 0; kc < D / KC; kc++) {
                __syncthreads();   // prior Wb readers done
                // stage W chunk [G4][KC]: LDG.128 + 2x STS.64
                // (Wb rows only 8B-aligned: stride 66 floats => NO float4 stores)
                for (int i = tid; i < G4 * (KC / 4); i += NT) {
                    int c = i >> 4, v = i & 15;
                    float4 wv = *(const float4*)(W + c * D + kc * KC + v * 4);
                    ull* dst = (ull*)(Wb + c * WP + v * 4);   // 8B aligned
                    dst[0] = pk2(wv.x, wv.y);
                    dst[1] = pk2(wv.z, wv.w);
                }
                __syncthreads();

                const float* Ak = A + kc * KC;
                const float* wl = Wb + lane * WP;   // lane's column base
                #pragma unroll 2
                for (int kp = 0; kp < KC / 2; kp++) {
                    // a pairs: broadcast LDS.64 per graph row
                    ull a0 = *(const ull*)(Ak + 0 * AP + 2 * kp);
                    ull a1 = *(const ull*)(Ak + 1 * AP + 2 * kp);
                    ull a2 = *(const ull*)(Ak + 2 * AP + 2 * kp);
                    ull a3 = *(const ull*)(Ak + 3 * AP + 2 * kp);
                    const float* wk = wl + 2 * kp;
                    #pragma unroll
                    for (int q = 0; q < 16; q++) {
                        const int off = ((q >> 2) * 128 + (q & 3) * 32) * WP;
                        ull b2 = *(const ull*)(wk + off);   // LDS.64, banks 2l,2l+1
                        fma2(acc[0][q], a0, b2);
                        fma2(acc[1][q], a1, b2);
                        fma2(acc[2][q], a2, b2);
                        fma2(acc[3][q], a3, b2);
                    }
                }
            }
        }
        __syncthreads();   // all Hs reads done before rewriting Hs

        // ---- activations, state update, score, hidden-state spill ----
        #pragma unroll
        for (int r = 0; r < 4; r++) {
            float sc = 0.0f;
            #pragma unroll
            for (int jj = 0; jj < 4; jj++) {
                float iv = sigf(upk_sum(acc[r][0 * 4 + jj]));
                float fv = sigf(upk_sum(acc[r][1 * 4 + jj]));
                float gv = tanhf_(upk_sum(acc[r][2 * 4 + jj]));
                float ov = sigf(upk_sum(acc[r][3 * 4 + jj]));
                float c  = fv * creg[r][jj] + iv * gv;
                creg[r][jj] = c;
                float h  = ov * tanhf_(c);
                int j = jj * 32 + lane;
                Hs[(g0 + r) * AP + j] = h;
                hs_buf[((size_t)(graph0 + g0 + r) * L + t) * D + j] = h;
                sc = fmaf(h, Wa[j], sc);
            }
            #pragma unroll
            for (int o = 16; o; o >>= 1)
                sc += __shfl_xor_sync(0xffffffffu, sc, o);
            if (lane == 0) Sc[(g0 + r) * L + t] = sc + batt;
        }
    }
    __syncthreads();

    // ---- attention pooling: each warp handles its own 4 graphs ----
    #pragma unroll 1
    for (int r = 0; r < 4; r++) {
        int g = g0 + r;
        float s1 = Sc[g * L + lane], s2 = Sc[g * L + 32 + lane];
        float m = fmaxf(s1, s2);
        #pragma unroll
        for (int o = 16; o; o >>= 1)
            m = fmaxf(m, __shfl_xor_sync(0xffffffffu, m, o));
        float e1 = ex2a(1.4426950408889634f * (s1 - m));
        float e2 = ex2a(1.4426950408889634f * (s2 - m));
        float z = e1 + e2;
        #pragma unroll
        for (int o = 16; o; o >>= 1)
            z += __shfl_xor_sync(0xffffffffu, z, o);
        float inv = rcpa(z);
        Sc[g * L + lane] = e1 * inv;
        Sc[g * L + 32 + lane] = e2 * inv;
        __syncwarp();

        float a0 = 0.f, a1 = 0.f, a2 = 0.f, a3 = 0.f;
        const float* hp = hs_buf + (size_t)(graph0 + g) * L * D;
        for (int tt = 0; tt < L; tt++) {
            float wt = Sc[g * L + tt];
            a0 = fmaf(wt, hp[tt * D +  0 + lane], a0);
            a1 = fmaf(wt, hp[tt * D + 32 + lane], a1);
            a2 = fmaf(wt, hp[tt * D + 64 + lane], a2);
            a3 = fmaf(wt, hp[tt * D + 96 + lane], a3);
        }
        float* op = out + (size_t)(graph0 + g) * D;
        op[ 0 + lane] = a0;
        op[32 + lane] = a1;
        op[64 + lane] = a2;
        op[96 + lane] = a3;
    }
}

extern "C" void kernel_launch(void* const* d_in, const int* in_sizes, int n_in,
                              void* d_out, int out_size)
{
    const float* x     = (const float*)d_in[0];
    // d_in[1] = batch (int32) -- structurally arange(N)//L, unused
    const float* W_ih  = (const float*)d_in[2];
    const float* W_hh  = (const float*)d_in[3];
    const float* b_ih  = (const float*)d_in[4];
    const float* b_hh  = (const float*)d_in[5];
    const float* W_att = (const float*)d_in[6];
    const float* b_att = (const float*)d_in[7];
    float* out = (float*)d_out;

    cudaFuncSetAttribute(lstm_att_kernel,
                         cudaFuncAttributeMaxDynamicSharedMemorySize, SMEM_BYTES);
    lstm_att_kernel<<<NG / GB, NT, SMEM_BYTES>>>(
        x, W_ih, W_hh, b_ih, b_hh, W_att, b_att, out);
}

// round 7
// speedup vs baseline: 3.5495x; 3.1520x over previous
#include <cuda_runtime.h>
#include <cuda_bf16.h>
#include <cstdint>
#include <string.h>

typedef unsigned long long ull;
typedef unsigned int uint;

#define L    64
#define NGR  8192
#define HD   128
#define MM   64             // graphs per CTA
#define NTH  512            // 16 warps

// ---- smem byte offsets ----
#define S_AHI  0            // A hi: 64 rows x 256 k bf16, SW128 blocked (32KB)
#define S_ALO  32768        // A lo (32KB)
#define S_WB0  65536        // W image buf 0 (64KB)
#define S_WB1  131072       // W image buf 1 (64KB)
#define S_BIAS 196608       // 512 floats
#define S_TOT  198656

// W images: [job = kc*2 + split][512 n][64 k] bf16, SW128 blocked. 8 x 64KB.
__device__ __align__(128) unsigned char wblob[8 * 65536];
__device__ float hs_buf[(size_t)NGR * L * HD];   // 256MB hidden states

// ---- PTX helpers (all base-PTX, sm_80-level: no tcgen05) ----
__device__ __forceinline__ uint smem_u32(const void* p) {
    uint a; asm("{ .reg .u64 t; cvta.to.shared.u64 t, %1; cvt.u32.u64 %0, t; }"
                : "=r"(a) : "l"(p));
    return a;
}
#define CP_ASYNC16(dst, src) \
    asm volatile("cp.async.cg.shared.global [%0], [%1], 16;" :: "r"(dst), "l"(src))
#define CP_COMMIT() asm volatile("cp.async.commit_group;" ::: "memory")
#define CP_WAIT(n)  asm volatile("cp.async.wait_group %0;" :: "n"(n) : "memory")

__device__ __forceinline__ void ldmx4(uint* r, uint addr) {
    asm volatile("ldmatrix.sync.aligned.m8n8.x4.shared.b16 {%0,%1,%2,%3}, [%4];"
        : "=r"(r[0]), "=r"(r[1]), "=r"(r[2]), "=r"(r[3]) : "r"(addr));
}
// B is stored K-major ([n][k], k contiguous): NON-trans ldmatrix gives the
// .col B fragment directly (lane l -> B[k=2(l&3)+e][n=l>>2]).
__device__ __forceinline__ void ldmx2(uint* r, uint addr) {
    asm volatile("ldmatrix.sync.aligned.m8n8.x2.shared.b16 {%0,%1}, [%2];"
        : "=r"(r[0]), "=r"(r[1]) : "r"(addr));
}
__device__ __forceinline__ void mma16816(float* d, const uint* a, const uint* b) {
    asm volatile(
        "mma.sync.aligned.m16n8k16.row.col.f32.bf16.bf16.f32 "
        "{%0,%1,%2,%3}, {%4,%5,%6,%7}, {%8,%9}, {%0,%1,%2,%3};"
        : "+f"(d[0]), "+f"(d[1]), "+f"(d[2]), "+f"(d[3])
        : "r"(a[0]), "r"(a[1]), "r"(a[2]), "r"(a[3]), "r"(b[0]), "r"(b[1]));
}
// ---- MUFU activations (rel err ~1e-7) ----
__device__ __forceinline__ float ex2a(float x) { float y; asm("ex2.approx.f32 %0, %1;" : "=f"(y) : "f"(x)); return y; }
__device__ __forceinline__ float rcpa(float x) { float y; asm("rcp.approx.f32 %0, %1;" : "=f"(y) : "f"(x)); return y; }
__device__ __forceinline__ float sigf(float x)  { return rcpa(1.0f + ex2a(-1.4426950408889634f * x)); }
__device__ __forceinline__ float tanhf_(float x){ return fmaf(2.0f, rcpa(1.0f + ex2a(-2.8853900817779268f * x)), -1.0f); }

__device__ __forceinline__ uint pk2bf(float a, float b) {
    __nv_bfloat162 p(__float2bfloat16(a), __float2bfloat16(b));
    uint u; memcpy(&u, &p, 4); return u;
}
// A tile byte offset: 64 rows x 256 k bf16; atoms 8r x 64k; SW128 swizzle
__device__ __forceinline__ uint a_off(int r, int k) {
    uint b = (uint)(((((r >> 3) + (k >> 6) * 8)) << 10) + ((r & 7) << 7) + ((k & 63) << 1));
    return b ^ ((b >> 3) & 0x70);
}
// W image byte offset: 512 n x 64 k bf16; atoms 8n x 64k
__device__ __forceinline__ uint w_off(int n, int k) {
    uint b = (uint)(((n >> 3) << 10) + ((n & 7) << 7) + (k << 1));
    return b ^ ((b >> 3) & 0x70);
}

// ============ W prep: split hi/lo, swizzle into 8 images ============
extern "C" __global__ void prep_kernel(const float* __restrict__ W_ih,
                                       const float* __restrict__ W_hh)
{
    int i = blockIdx.x * blockDim.x + threadIdx.x;   // 512*256
    if (i >= 512 * 256) return;
    int n = i >> 8, k = i & 255;
    float w = (k < 128) ? W_ih[n * 128 + k] : W_hh[n * 128 + (k - 128)];
    __nv_bfloat16 hi = __float2bfloat16(w);
    __nv_bfloat16 lo = __float2bfloat16(w - __bfloat162float(hi));
    uint off = w_off(n, k & 63);
    int kc = k >> 6;
    *(__nv_bfloat16*)(wblob + (size_t)(kc * 2 + 0) * 65536 + off) = hi;
    *(__nv_bfloat16*)(wblob + (size_t)(kc * 2 + 1) * 65536 + off) = lo;
}

// ============ LSTM recurrence (mma.sync bf16, 3-term split) ============
extern "C" __global__ void __launch_bounds__(NTH, 1)
lstm_mma_kernel(const float* __restrict__ x,
                const float* __restrict__ b_ih,
                const float* __restrict__ b_hh)
{
    extern __shared__ __align__(1024) char sm[];
    const uint smb  = smem_u32(sm);
    const int tid   = threadIdx.x;
    const int lane  = tid & 31;
    const int warp  = tid >> 5;       // 0..15: col-slice within each gate
    const int graph0 = blockIdx.x * MM;
    float* Bi = (float*)(sm + S_BIAS);

    if (tid < 512) Bi[tid] = b_ih[tid] + b_hh[tid];
    // zero h-region of A (k 128..255 = atom-cols 2,3 = bytes [16384,32768))
    #pragma unroll
    for (int it = 0; it < 4; it++) {
        ((ull*)(sm + S_AHI + 16384))[tid + it * NTH] = 0ull;
        ((ull*)(sm + S_ALO + 16384))[tid + it * NTH] = 0ull;
    }

    // ---- per-lane ldmatrix address components ----
    // A (x4): lanes 0-7: m0-7/kseg0; 8-15: m8-15/kseg0; 16-23: m0-7/kseg1; 24-31: m8-15/kseg1
    const int rA    = (lane & 7);                 // row within 8-row atom group
    const int mHalf = (lane >> 3) & 1;            // +8 rows
    const int aKsel = (lane >> 4) << 4;           // kseg byte (0|16)
    const uint aPre = (uint)((rA << 7));          // (r&7)*128
    const uint swA  = (uint)(rA << 4);
    // B (x2): lanes 0-7: n0-7/kseg0; 8-15: n0-7/kseg1
    const int lb    = lane & 15;
    const uint bPre = (uint)((lb & 7) << 7) + ((uint)warp << 10);  // + warp atom
    const uint swB  = (uint)((lb & 7) << 4);
    const int bKsel = ((lb >> 3) & 1) << 4;

    // per-thread output coords
    const int jj = (lane & 3) << 1;               // col pair within warp's 8 cols
    const int j0 = (warp << 3) + jj;              // hidden index (even)
    const int rowq = lane >> 2;                   // 0..7

    float creg[4][4];                              // [mt][rg*2+cp]
    #pragma unroll
    for (int a = 0; a < 4; a++)
        #pragma unroll
        for (int b = 0; b < 4; b++) creg[a][b] = 0.0f;

    // bias seeds (per gate, per col-pair element)
    float bseed[4][2];
    __syncthreads();
    #pragma unroll
    for (int gt = 0; gt < 4; gt++) {
        bseed[gt][0] = Bi[gt * 128 + j0];
        bseed[gt][1] = Bi[gt * 128 + j0 + 1];
    }

    for (int t = 0; t < L; t++) {
        // prefetch W image 0 into buf0 (overlaps x staging)
        {
            const char* src = (const char*)wblob + tid * 16;
            uint dst = smb + S_WB0 + tid * 16;
            #pragma unroll
            for (int it = 0; it < 8; it++)
                CP_ASYNC16(dst + it * 8192, src + it * 8192);
            CP_COMMIT();
        }
        // ---- stage x_t: 64 graphs x 128 fp32 -> A k[0..127] hi/lo ----
        #pragma unroll
        for (int it = 0; it < 4; it++) {
            int idx = tid + it * NTH;              // over 2048 float4
            int g = idx >> 5, v = idx & 31;
            float4 xv = *(const float4*)(x + ((size_t)(graph0 + g) * L + t) * HD + v * 4);
            float fx = __bfloat162float(__float2bfloat16(xv.x));
            float fy = __bfloat162float(__float2bfloat16(xv.y));
            float fz = __bfloat162float(__float2bfloat16(xv.z));
            float fw = __bfloat162float(__float2bfloat16(xv.w));
            uint off = a_off(g, v * 4);
            *(ull*)(sm + S_AHI + off) = (ull)pk2bf(fx, fy) | ((ull)pk2bf(fz, fw) << 32);
            *(ull*)(sm + S_ALO + off) =
                (ull)pk2bf(xv.x - fx, xv.y - fy) | ((ull)pk2bf(xv.z - fz, xv.w - fw) << 32);
        }

        // ---- accumulators seeded with bias ----
        float acc[4][4][4];                        // [mt][gt][frag]
        #pragma unroll
        for (int mt = 0; mt < 4; mt++)
            #pragma unroll
            for (int gt = 0; gt < 4; gt++) {
                acc[mt][gt][0] = bseed[gt][0]; acc[mt][gt][1] = bseed[gt][1];
                acc[mt][gt][2] = bseed[gt][0]; acc[mt][gt][3] = bseed[gt][1];
            }

        // ---- 8 jobs: kc(4) x split(hi,lo), cp.async double-buffered ----
        for (int j = 0; j < 8; j++) {
            if (j + 1 < 8) {   // issue next image
                const char* src = (const char*)wblob + (size_t)(j + 1) * 65536 + tid * 16;
                uint dst = smb + ((j + 1) & 1 ? S_WB1 : S_WB0) + tid * 16;
                #pragma unroll
                for (int it = 0; it < 8; it++)
                    CP_ASYNC16(dst + it * 8192, src + it * 8192);
                CP_COMMIT();
                CP_WAIT(1);
            } else {
                CP_WAIT(0);
            }
            __syncthreads();                       // image j visible to all

            const int kc = j >> 1, s = j & 1;
            const uint wb = smb + ((j & 1) ? S_WB1 : S_WB0);
            const uint aAtomBase = (uint)((mHalf + kc * 8) << 10);

            #pragma unroll
            for (int ks = 0; ks < 4; ks++) {
                // B frags: 4 gate tiles (atom = gt*16 + warp)
                uint bfr[4][2];
                const uint bLow = (uint)(((ks << 5) + bKsel)) ^ swB;
                #pragma unroll
                for (int gt = 0; gt < 4; gt++)
                    ldmx2(bfr[gt], wb + (uint)(gt << 14) + bPre + bLow);

                const uint aLow = (uint)(((ks << 5) + aKsel)) ^ swA;
                if (s == 0) {                      // hi image: Ahi*Whi + Alo*Whi
                    #pragma unroll
                    for (int mt = 0; mt < 4; mt++) {
                        uint ah[4], al[4];
                        uint aoff = aAtomBase + (uint)(mt << 11) + aPre + aLow;
                        ldmx4(ah, smb + S_AHI + aoff);
                        ldmx4(al, smb + S_ALO + aoff);
                        #pragma unroll
                        for (int gt = 0; gt < 4; gt++) {
                            mma16816(acc[mt][gt], ah, bfr[gt]);
                            mma16816(acc[mt][gt], al, bfr[gt]);
                        }
                    }
                } else {                           // lo image: Ahi*Wlo
                    #pragma unroll
                    for (int mt = 0; mt < 4; mt++) {
                        uint ah[4];
                        uint aoff = aAtomBase + (uint)(mt << 11) + aPre + aLow;
                        ldmx4(ah, smb + S_AHI + aoff);
                        #pragma unroll
                        for (int gt = 0; gt < 4; gt++)
                            mma16816(acc[mt][gt], ah, bfr[gt]);
                    }
                }
            }
            __syncthreads();                       // all warps done with buf before refill
        }

        // ---- epilogue: lane-local LSTM update ----
        #pragma unroll
        for (int mt = 0; mt < 4; mt++) {
            #pragma unroll
            for (int rg = 0; rg < 2; rg++) {
                float h2[2];
                #pragma unroll
                for (int cp = 0; cp < 2; cp++) {
                    const int fr = rg * 2 + cp;
                    float iv = sigf (acc[mt][0][fr]);
                    float fv = sigf (acc[mt][1][fr]);
                    float gv = tanhf_(acc[mt][2][fr]);
                    float ov = sigf (acc[mt][3][fr]);
                    float c  = fv * creg[mt][fr] + iv * gv;
                    creg[mt][fr] = c;
                    h2[cp] = ov * tanhf_(c);
                }
                const int g = mt * 16 + rg * 8 + rowq;
                // h -> A (bf16 hi/lo) at k = 128 + j0
                float f0 = __bfloat162float(__float2bfloat16(h2[0]));
                float f1 = __bfloat162float(__float2bfloat16(h2[1]));
                uint off = a_off(g, 128 + j0);
                *(uint*)(sm + S_AHI + off) = pk2bf(f0, f1);
                *(uint*)(sm + S_ALO + off) = pk2bf(h2[0] - f0, h2[1] - f1);
                // h -> hs_buf fp32
                *(float2*)(hs_buf + ((size_t)(graph0 + g) * L + t) * HD + j0)
                    = make_float2(h2[0], h2[1]);
            }
        }
        __syncthreads();   // h writes visible before next step's MMAs
    }
}

// ============ attention pooling over hs_buf ============
extern "C" __global__ void __launch_bounds__(256)
att_kernel(const float* __restrict__ W_att, const float* __restrict__ b_att,
           float* __restrict__ out)
{
    __shared__ float Wa[HD];
    __shared__ float Sc[32 * L];
    const int tid = threadIdx.x, lane = tid & 31, warp = tid >> 5;
    const int graph0 = blockIdx.x * 32;
    const int g0 = warp << 2;
    if (tid < HD) Wa[tid] = W_att[tid];
    const float batt = b_att[0];
    __syncthreads();

    #pragma unroll 1
    for (int r = 0; r < 4; r++) {
        const int g = g0 + r;
        const size_t gg = (size_t)(graph0 + g);
        const float* hp = hs_buf + gg * L * HD;
        const float4 wv = *(const float4*)(Wa + lane * 4);
        for (int t = 0; t < L; t++) {
            float4 hv = *(const float4*)(hp + t * HD + lane * 4);
            float d = hv.x * wv.x + hv.y * wv.y + hv.z * wv.z + hv.w * wv.w;
            #pragma unroll
            for (int o = 16; o; o >>= 1)
                d += __shfl_xor_sync(0xffffffffu, d, o);
            if (lane == 0) Sc[g * L + t] = d + batt;
        }
        __syncwarp();
        float s1 = Sc[g * L + lane], s2 = Sc[g * L + 32 + lane];
        float m = fmaxf(s1, s2);
        #pragma unroll
        for (int o = 16; o; o >>= 1)
            m = fmaxf(m, __shfl_xor_sync(0xffffffffu, m, o));
        float e1 = ex2a(1.4426950408889634f * (s1 - m));
        float e2 = ex2a(1.4426950408889634f * (s2 - m));
        float z = e1 + e2;
        #pragma unroll
        for (int o = 16; o; o >>= 1)
            z += __shfl_xor_sync(0xffffffffu, z, o);
        float inv = rcpa(z);
        Sc[g * L + lane] = e1 * inv;
        Sc[g * L + 32 + lane] = e2 * inv;
        __syncwarp();
        float a0 = 0.f, a1 = 0.f, a2 = 0.f, a3 = 0.f;
        for (int tt = 0; tt < L; tt++) {
            float wt = Sc[g * L + tt];
            a0 = fmaf(wt, hp[tt * HD +  0 + lane], a0);
            a1 = fmaf(wt, hp[tt * HD + 32 + lane], a1);
            a2 = fmaf(wt, hp[tt * HD + 64 + lane], a2);
            a3 = fmaf(wt, hp[tt * HD + 96 + lane], a3);
        }
        float* op = out + gg * HD;
        op[ 0 + lane] = a0;
        op[32 + lane] = a1;
        op[64 + lane] = a2;
        op[96 + lane] = a3;
    }
}

extern "C" void kernel_launch(void* const* d_in, const int* in_sizes, int n_in,
                              void* d_out, int out_size)
{
    const float* x     = (const float*)d_in[0];
    // d_in[1] = batch (arange(N)//L), unused
    const float* W_ih  = (const float*)d_in[2];
    const float* W_hh  = (const float*)d_in[3];
    const float* b_ih  = (const float*)d_in[4];
    const float* b_hh  = (const float*)d_in[5];
    const float* W_att = (const float*)d_in[6];
    const float* b_att = (const float*)d_in[7];
    float* out = (float*)d_out;

    prep_kernel<<<512, 256>>>(W_ih, W_hh);
    cudaFuncSetAttribute(lstm_mma_kernel,
                         cudaFuncAttributeMaxDynamicSharedMemorySize, S_TOT);
    lstm_mma_kernel<<<NGR / MM, NTH, S_TOT>>>(x, b_ih, b_hh);
    att_kernel<<<NGR / 32, 256>>>(W_att, b_att, out);
}